// round 1
// baseline (speedup 1.0000x reference)
#include <cuda_runtime.h>
#include <cstdint>

// GlobalFilter: y = irfft(rfft(x, n=10) * W, n=10)  ==  per-dim circular conv of length 10.
// x: [B=8192, DIM=1024, N=10] f32, W: [DIM, 6, 2] f32, y: [B, DIM, 10] f32.

#define DIM   1024
#define NPTS  10

// h stored pair-interleaved: for pair p (dims 2p, 2p+1), 10 float2 entries:
//   g_h[p*20 + j*2 + 0] = h[2p][j],  g_h[p*20 + j*2 + 1] = h[2p+1][j]
__device__ float g_h[DIM * NPTS];

__device__ __constant__ float COS10[10] = {
    1.0f,  0.80901699437494745f,  0.30901699437494745f, -0.30901699437494745f, -0.80901699437494745f,
   -1.0f, -0.80901699437494745f, -0.30901699437494745f,  0.30901699437494745f,  0.80901699437494745f};
__device__ __constant__ float SIN10[10] = {
    0.0f,  0.58778525229247314f,  0.95105651629515357f,  0.95105651629515357f,  0.58778525229247314f,
    0.0f, -0.58778525229247314f, -0.95105651629515357f, -0.95105651629515357f, -0.58778525229247314f};

__global__ void precompute_h_kernel(const float* __restrict__ w) {
    int d = blockIdx.x * blockDim.x + threadIdx.x;
    if (d >= DIM) return;
    // w[d] = 12 floats (6 complex), 48-byte offset -> 16B aligned
    const float4* wp = reinterpret_cast<const float4*>(w + d * 12);
    float4 w0 = wp[0], w1 = wp[1], w2 = wp[2];
    float a[6], b[6];
    a[0] = w0.x; b[0] = w0.y; a[1] = w0.z; b[1] = w0.w;
    a[2] = w1.x; b[2] = w1.y; a[3] = w1.z; b[3] = w1.w;
    a[4] = w2.x; b[4] = w2.y; a[5] = w2.z; b[5] = w2.w;

    int base = (d >> 1) * 20 + (d & 1);
#pragma unroll
    for (int j = 0; j < NPTS; j++) {
        float acc = a[0] + ((j & 1) ? -a[5] : a[5]);
#pragma unroll
        for (int k = 1; k <= 4; k++) {
            int m = (k * j) % 10;
            acc += 2.0f * (a[k] * COS10[m] - b[k] * SIN10[m]);
        }
        g_h[base + j * 2] = 0.1f * acc;
    }
}

// ---- packed f32x2 helpers ----
__device__ __forceinline__ unsigned long long pack2(float lo, float hi) {
    unsigned long long r;
    asm("mov.b64 %0, {%1, %2};" : "=l"(r) : "f"(lo), "f"(hi));
    return r;
}
__device__ __forceinline__ void unpack2(unsigned long long v, float& lo, float& hi) {
    asm("mov.b64 {%0, %1}, %2;" : "=f"(lo), "=f"(hi) : "l"(v));
}
__device__ __forceinline__ unsigned long long fma2(unsigned long long a,
                                                   unsigned long long b,
                                                   unsigned long long c) {
    unsigned long long d;
    asm("fma.rn.f32x2 %0, %1, %2, %3;" : "=l"(d) : "l"(a), "l"(b), "l"(c));
    return d;
}

// Each thread processes rows 2t and 2t+1 (same batch, adjacent dims since DIM is even).
__global__ void __launch_bounds__(256) global_filter_kernel(const float* __restrict__ x,
                                                            float* __restrict__ y) {
    int t = blockIdx.x * blockDim.x + threadIdx.x;

    // Load 20 floats (two rows) as 5x float4; base offset t*80 bytes is 16B aligned.
    const float4* xp = reinterpret_cast<const float4*>(x) + (size_t)t * 5;
    float4 v0 = xp[0], v1 = xp[1], v2 = xp[2], v3 = xp[3], v4 = xp[4];

    float x0[10] = {v0.x, v0.y, v0.z, v0.w, v1.x, v1.y, v1.z, v1.w, v2.x, v2.y};
    float x1[10] = {v2.z, v2.w, v3.x, v3.y, v3.z, v3.w, v4.x, v4.y, v4.z, v4.w};

    unsigned long long xv[10];
#pragma unroll
    for (int j = 0; j < 10; j++) xv[j] = pack2(x0[j], x1[j]);

    // h pair index: row0 = 2t -> d0 = (2t) % DIM, pair p = d0/2 = t % (DIM/2)
    int p = t & (DIM / 2 - 1);
    const ulonglong2* hp = reinterpret_cast<const ulonglong2*>(g_h) + (size_t)p * 5;
    ulonglong2 h01 = hp[0], h23 = hp[1], h45 = hp[2], h67 = hp[3], h89 = hp[4];
    unsigned long long hv[10] = {h01.x, h01.y, h23.x, h23.y, h45.x,
                                 h45.y, h67.x, h67.y, h89.x, h89.y};

    unsigned long long acc[10];
#pragma unroll
    for (int n = 0; n < 10; n++) acc[n] = 0ULL;  // +0.0f,+0.0f packed

#pragma unroll
    for (int j = 0; j < 10; j++) {
#pragma unroll
        for (int n = 0; n < 10; n++) {
            acc[n] = fma2(hv[(n - j + 10) % 10], xv[j], acc[n]);
        }
    }

    float y0[10], y1[10];
#pragma unroll
    for (int n = 0; n < 10; n++) unpack2(acc[n], y0[n], y1[n]);

    float4* yp = reinterpret_cast<float4*>(y) + (size_t)t * 5;
    yp[0] = make_float4(y0[0], y0[1], y0[2], y0[3]);
    yp[1] = make_float4(y0[4], y0[5], y0[6], y0[7]);
    yp[2] = make_float4(y0[8], y0[9], y1[0], y1[1]);
    yp[3] = make_float4(y1[2], y1[3], y1[4], y1[5]);
    yp[4] = make_float4(y1[6], y1[7], y1[8], y1[9]);
}

extern "C" void kernel_launch(void* const* d_in, const int* in_sizes, int n_in,
                              void* d_out, int out_size) {
    const float* x = (const float*)d_in[0];
    const float* w = (const float*)d_in[1];
    float* y = (float*)d_out;

    precompute_h_kernel<<<(DIM + 255) / 256, 256>>>(w);

    int nrows = in_sizes[0] / NPTS;      // 8192*1024
    int pairs = nrows / 2;               // 4,194,304
    global_filter_kernel<<<pairs / 256, 256>>>(x, y);
}